// round 9
// baseline (speedup 1.0000x reference)
#include <cuda_runtime.h>

#define NS   256     // batch
#define INF_ 1024    // in_features
#define BF   128     // B (kernels)
#define CF   16      // C (dims per kernel)
#define BC   2048    // B*C
#define OUTW (INF_ + BF)  // 1152

// Scratch for mat = x @ T  (256 x 2048 fp32 = 2 MB)
__device__ float g_mat[NS * BC];

// ---------------------------------------------------------------------------
// GEMM: g_mat[m][j] = sum_k x[m][k] * T[k][j]
// 64x64 block tile, BK=16, 256 threads, 4x4 per thread, register prefetch.
// ---------------------------------------------------------------------------
__global__ __launch_bounds__(256) void gemm_kernel(const float* __restrict__ X,
                                                   const float* __restrict__ T) {
    __shared__ float As[16][68];   // [k][m], padded: conflict-light, 16B-aligned rows
    __shared__ float Bs[16][64];   // [k][n]

    const int tid  = threadIdx.x;
    const int tx   = tid & 15;     // 0..15 -> 4 output cols each
    const int ty   = tid >> 4;     // 0..15 -> 4 output rows each
    const int m0   = blockIdx.y << 6;
    const int n0   = blockIdx.x << 6;

    // loader mapping
    const int arow = tid >> 2, aseg = tid & 3;    // A tile: 64 rows x 4 float4
    const int brow = tid >> 4, bcol = tid & 15;   // B tile: 16 rows x 16 float4

    const float* aptr = X + (m0 + arow) * INF_ + aseg * 4;
    const float* bptr = T + brow * BC + n0 + bcol * 4;

    float4 a = *(const float4*)(aptr);
    float4 b = *(const float4*)(bptr);

    float acc[4][4] = {};

    for (int k0 = 0; k0 < INF_; k0 += 16) {
        // stage current tile
        As[aseg * 4 + 0][arow] = a.x;
        As[aseg * 4 + 1][arow] = a.y;
        As[aseg * 4 + 2][arow] = a.z;
        As[aseg * 4 + 3][arow] = a.w;
        *(float4*)&Bs[brow][bcol * 4] = b;
        __syncthreads();

        // prefetch next tile into registers (hides GMEM latency under compute)
        if (k0 + 16 < INF_) {
            a = *(const float4*)(aptr + (k0 + 16));
            b = *(const float4*)(bptr + (size_t)(k0 + 16) * BC);
        }

        #pragma unroll
        for (int kk = 0; kk < 16; kk++) {
            float4 a4 = *(const float4*)&As[kk][ty * 4];   // broadcast LDS
            float4 b4 = *(const float4*)&Bs[kk][tx * 4];
            float av[4] = {a4.x, a4.y, a4.z, a4.w};
            float bv[4] = {b4.x, b4.y, b4.z, b4.w};
            #pragma unroll
            for (int i = 0; i < 4; i++)
                #pragma unroll
                for (int j = 0; j < 4; j++)
                    acc[i][j] += av[i] * bv[j];
        }
        __syncthreads();
    }

    #pragma unroll
    for (int i = 0; i < 4; i++) {
        float4 v = make_float4(acc[i][0], acc[i][1], acc[i][2], acc[i][3]);
        *(float4*)&g_mat[(size_t)(m0 + ty * 4 + i) * BC + n0 + tx * 4] = v;
    }
}

// ---------------------------------------------------------------------------
// Pairwise: o[n][b] = sum_m exp(-sum_c |mat[n,b,c] - mat[m,b,c]|)
// One block per b. Stage mat[:, b, :] (256x16) in SMEM; each thread owns row n
// in registers; m-loop reads are uniform -> broadcast LDS.128.
// ---------------------------------------------------------------------------
__global__ __launch_bounds__(256) void pair_kernel(float* __restrict__ out) {
    __shared__ float s[NS][20];    // pad 20: 16B-aligned rows, spread store banks

    const int b = blockIdx.x;
    const int n = threadIdx.x;

    const float* row = g_mat + (size_t)n * BC + b * CF;
    float4 r0 = *(const float4*)(row + 0);
    float4 r1 = *(const float4*)(row + 4);
    float4 r2 = *(const float4*)(row + 8);
    float4 r3 = *(const float4*)(row + 12);

    *(float4*)&s[n][0]  = r0;
    *(float4*)&s[n][4]  = r1;
    *(float4*)&s[n][8]  = r2;
    *(float4*)&s[n][12] = r3;
    __syncthreads();

    float acc = 0.f;
    #pragma unroll 4
    for (int m = 0; m < NS; m++) {
        const float* q = s[m];
        float4 q0 = *(const float4*)(q + 0);
        float4 q1 = *(const float4*)(q + 4);
        float4 q2 = *(const float4*)(q + 8);
        float4 q3 = *(const float4*)(q + 12);

        // tree-reduce to keep the dependency chain short (~6 FADD deep)
        float d0 = fabsf(r0.x - q0.x) + fabsf(r0.y - q0.y);
        float d1 = fabsf(r0.z - q0.z) + fabsf(r0.w - q0.w);
        float d2 = fabsf(r1.x - q1.x) + fabsf(r1.y - q1.y);
        float d3 = fabsf(r1.z - q1.z) + fabsf(r1.w - q1.w);
        float d4 = fabsf(r2.x - q2.x) + fabsf(r2.y - q2.y);
        float d5 = fabsf(r2.z - q2.z) + fabsf(r2.w - q2.w);
        float d6 = fabsf(r3.x - q3.x) + fabsf(r3.y - q3.y);
        float d7 = fabsf(r3.z - q3.z) + fabsf(r3.w - q3.w);
        float e0 = (d0 + d1) + (d2 + d3);
        float e1 = (d4 + d5) + (d6 + d7);
        acc += __expf(-(e0 + e1));     // self term m==n gives exp(0)=1 exactly
    }

    out[(size_t)n * OUTW + INF_ + b] = acc;
}

// ---------------------------------------------------------------------------
// Copy: out[n][0:1024] = x[n][:]
// ---------------------------------------------------------------------------
__global__ __launch_bounds__(256) void copy_kernel(const float* __restrict__ X,
                                                   float* __restrict__ out) {
    const int n = blockIdx.x;
    const int t = threadIdx.x;
    float4 v = *(const float4*)(X + (size_t)n * INF_ + t * 4);
    *(float4*)(out + (size_t)n * OUTW + t * 4) = v;
}

extern "C" void kernel_launch(void* const* d_in, const int* in_sizes, int n_in,
                              void* d_out, int out_size) {
    const float* x = (const float*)d_in[0];   // [256, 1024] fp32
    const float* T = (const float*)d_in[1];   // [1024, 128, 16] fp32
    float* out = (float*)d_out;               // [256, 1152] fp32

    (void)in_sizes; (void)n_in; (void)out_size;

    dim3 gg(BC / 64, NS / 64);                // 32 x 4 = 128 blocks
    gemm_kernel<<<gg, 256>>>(x, T);
    copy_kernel<<<NS, 256>>>(x, out);         // independent of g_mat
    pair_kernel<<<BF, 256>>>(out);            // consumes g_mat (same-stream order)
}

// round 12
// speedup vs baseline: 1.0044x; 1.0044x over previous
#include <cuda_runtime.h>

#define NS   256     // batch
#define INF_ 1024    // in_features
#define BF   128     // B (kernels)
#define CF   16      // C (dims per kernel)
#define BC   2048    // B*C
#define OUTW (INF_ + BF)  // 1152

// Scratch for mat = x @ T  (256 x 2048 fp32 = 2 MB)
__device__ float g_mat[NS * BC];

// ---------------------------------------------------------------------------
// GEMM: g_mat[m][j] = sum_k x[m][k] * T[k][j]
// 64x64 block tile, BK=16, 256 threads, 4x4 per thread, register prefetch.
// ---------------------------------------------------------------------------
__global__ __launch_bounds__(256) void gemm_kernel(const float* __restrict__ X,
                                                   const float* __restrict__ T) {
    __shared__ float As[16][68];   // [k][m], padded: conflict-light, 16B-aligned rows
    __shared__ float Bs[16][64];   // [k][n]

    const int tid  = threadIdx.x;
    const int tx   = tid & 15;     // 0..15 -> 4 output cols each
    const int ty   = tid >> 4;     // 0..15 -> 4 output rows each
    const int m0   = blockIdx.y << 6;
    const int n0   = blockIdx.x << 6;

    // loader mapping
    const int arow = tid >> 2, aseg = tid & 3;    // A tile: 64 rows x 4 float4
    const int brow = tid >> 4, bcol = tid & 15;   // B tile: 16 rows x 16 float4

    const float* aptr = X + (m0 + arow) * INF_ + aseg * 4;
    const float* bptr = T + brow * BC + n0 + bcol * 4;

    float4 a = *(const float4*)(aptr);
    float4 b = *(const float4*)(bptr);

    float acc[4][4] = {};

    for (int k0 = 0; k0 < INF_; k0 += 16) {
        // stage current tile
        As[aseg * 4 + 0][arow] = a.x;
        As[aseg * 4 + 1][arow] = a.y;
        As[aseg * 4 + 2][arow] = a.z;
        As[aseg * 4 + 3][arow] = a.w;
        *(float4*)&Bs[brow][bcol * 4] = b;
        __syncthreads();

        // prefetch next tile into registers (hides GMEM latency under compute)
        if (k0 + 16 < INF_) {
            a = *(const float4*)(aptr + (k0 + 16));
            b = *(const float4*)(bptr + (size_t)(k0 + 16) * BC);
        }

        #pragma unroll
        for (int kk = 0; kk < 16; kk++) {
            float4 a4 = *(const float4*)&As[kk][ty * 4];   // broadcast LDS
            float4 b4 = *(const float4*)&Bs[kk][tx * 4];
            float av[4] = {a4.x, a4.y, a4.z, a4.w};
            float bv[4] = {b4.x, b4.y, b4.z, b4.w};
            #pragma unroll
            for (int i = 0; i < 4; i++)
                #pragma unroll
                for (int j = 0; j < 4; j++)
                    acc[i][j] += av[i] * bv[j];
        }
        __syncthreads();
    }

    #pragma unroll
    for (int i = 0; i < 4; i++) {
        float4 v = make_float4(acc[i][0], acc[i][1], acc[i][2], acc[i][3]);
        *(float4*)&g_mat[(size_t)(m0 + ty * 4 + i) * BC + n0 + tx * 4] = v;
    }
}

// ---------------------------------------------------------------------------
// Pairwise: o[n][b] = sum_m exp(-sum_c |mat[n,b,c] - mat[m,b,c]|)
// One block per b. Stage mat[:, b, :] (256x16) in SMEM; each thread owns row n
// in registers; m-loop reads are uniform -> broadcast LDS.128.
// ---------------------------------------------------------------------------
__global__ __launch_bounds__(256) void pair_kernel(float* __restrict__ out) {
    __shared__ float s[NS][20];    // pad 20: 16B-aligned rows, spread store banks

    const int b = blockIdx.x;
    const int n = threadIdx.x;

    const float* row = g_mat + (size_t)n * BC + b * CF;
    float4 r0 = *(const float4*)(row + 0);
    float4 r1 = *(const float4*)(row + 4);
    float4 r2 = *(const float4*)(row + 8);
    float4 r3 = *(const float4*)(row + 12);

    *(float4*)&s[n][0]  = r0;
    *(float4*)&s[n][4]  = r1;
    *(float4*)&s[n][8]  = r2;
    *(float4*)&s[n][12] = r3;
    __syncthreads();

    float acc = 0.f;
    #pragma unroll 4
    for (int m = 0; m < NS; m++) {
        const float* q = s[m];
        float4 q0 = *(const float4*)(q + 0);
        float4 q1 = *(const float4*)(q + 4);
        float4 q2 = *(const float4*)(q + 8);
        float4 q3 = *(const float4*)(q + 12);

        // tree-reduce to keep the dependency chain short (~6 FADD deep)
        float d0 = fabsf(r0.x - q0.x) + fabsf(r0.y - q0.y);
        float d1 = fabsf(r0.z - q0.z) + fabsf(r0.w - q0.w);
        float d2 = fabsf(r1.x - q1.x) + fabsf(r1.y - q1.y);
        float d3 = fabsf(r1.z - q1.z) + fabsf(r1.w - q1.w);
        float d4 = fabsf(r2.x - q2.x) + fabsf(r2.y - q2.y);
        float d5 = fabsf(r2.z - q2.z) + fabsf(r2.w - q2.w);
        float d6 = fabsf(r3.x - q3.x) + fabsf(r3.y - q3.y);
        float d7 = fabsf(r3.z - q3.z) + fabsf(r3.w - q3.w);
        float e0 = (d0 + d1) + (d2 + d3);
        float e1 = (d4 + d5) + (d6 + d7);
        acc += __expf(-(e0 + e1));     // self term m==n gives exp(0)=1 exactly
    }

    out[(size_t)n * OUTW + INF_ + b] = acc;
}

// ---------------------------------------------------------------------------
// Copy: out[n][0:1024] = x[n][:]
// ---------------------------------------------------------------------------
__global__ __launch_bounds__(256) void copy_kernel(const float* __restrict__ X,
                                                   float* __restrict__ out) {
    const int n = blockIdx.x;
    const int t = threadIdx.x;
    float4 v = *(const float4*)(X + (size_t)n * INF_ + t * 4);
    *(float4*)(out + (size_t)n * OUTW + t * 4) = v;
}

extern "C" void kernel_launch(void* const* d_in, const int* in_sizes, int n_in,
                              void* d_out, int out_size) {
    const float* x = (const float*)d_in[0];   // [256, 1024] fp32
    const float* T = (const float*)d_in[1];   // [1024, 128, 16] fp32
    float* out = (float*)d_out;               // [256, 1152] fp32

    (void)in_sizes; (void)n_in; (void)out_size;

    dim3 gg(BC / 64, NS / 64);                // 32 x 4 = 128 blocks
    gemm_kernel<<<gg, 256>>>(x, T);
    copy_kernel<<<NS, 256>>>(x, out);         // independent of g_mat
    pair_kernel<<<BF, 256>>>(out);            // consumes g_mat (same-stream order)
}